// round 5
// baseline (speedup 1.0000x reference)
#include <cuda_runtime.h>

#define RANK 53
#define RPAD 56           // rank padded to 7 warps * 8
#define CIN  32
#define COUT 64
#define DIM  56
#define NVOX (56*56*56)   // 175616
#define STRH (56*56)
#define STRW 56
#define TH 8
#define TW 8
#define VOXT 256          // voxels per GEMM tile (NVOX/VOXT = 686 exact)

// Scratch: two rank-major intermediates [RANK][NVOX] (~35.5 MB each).
__device__ float g_bufA[RANK * NVOX];
__device__ float g_bufB[RANK * NVOX];

// ---------- packed f32x2 helpers (sm_103a) ----------
__device__ __forceinline__ unsigned long long pk2(float lo, float hi) {
    unsigned long long r;
    asm("mov.b64 %0, {%1, %2};" : "=l"(r) : "f"(lo), "f"(hi));
    return r;
}
__device__ __forceinline__ unsigned long long fma2(unsigned long long a,
                                                   unsigned long long b,
                                                   unsigned long long c) {
    unsigned long long d;
    asm("fma.rn.f32x2 %0, %1, %2, %3;" : "=l"(d) : "l"(a), "l"(b), "l"(c));
    return d;
}

// ---------- Kernel 1: pointwise Cin -> RANK ----------
// Warp w -> ranks [8w,8w+8). Lane owns voxels {lane*4..+3} and {lane*4+128..+3}
// (two contiguous 512B warp-quads -> conflict-free LDS.128 / coalesced STG.128).
__global__ __launch_bounds__(224, 2)
void k_pointwise(const float* __restrict__ x, const float* __restrict__ Ucin) {
    __shared__ float x_s[CIN * VOXT];                    // 32 KB
    __shared__ unsigned long long w_s[CIN * RPAD];       // 14 KB

    const int tid = threadIdx.x;
    const int vbase = blockIdx.x * VOXT;

    for (int i = tid; i < CIN * RPAD; i += 224) {
        int c = i / RPAD, r = i % RPAD;
        float v = (r < RANK) ? Ucin[c * RANK + r] : 0.f;
        w_s[i] = pk2(v, v);
    }
    for (int i = tid; i < CIN * (VOXT / 4); i += 224) {
        int c = i >> 6, q = i & 63;
        *(float4*)(x_s + c * VOXT + q * 4) =
            *(const float4*)(x + (size_t)c * NVOX + vbase + q * 4);
    }
    __syncthreads();

    const int warp = tid >> 5;
    const int lane = tid & 31;
    const int r0 = warp * 8;
    const int v0 = lane * 4;

    unsigned long long acc[8][4];
#pragma unroll
    for (int i = 0; i < 8; i++)
#pragma unroll
        for (int k = 0; k < 4; k++) acc[i][k] = 0ull;

#pragma unroll 2
    for (int c = 0; c < CIN; c++) {
        const unsigned long long* wp = w_s + c * RPAD + r0;
        ulonglong2 w01 = *(const ulonglong2*)(wp);
        ulonglong2 w23 = *(const ulonglong2*)(wp + 2);
        ulonglong2 w45 = *(const ulonglong2*)(wp + 4);
        ulonglong2 w67 = *(const ulonglong2*)(wp + 6);
        ulonglong2 xa  = *(const ulonglong2*)(x_s + c * VOXT + v0);
        ulonglong2 xb  = *(const ulonglong2*)(x_s + c * VOXT + v0 + 128);
        unsigned long long w[8] = {w01.x, w01.y, w23.x, w23.y, w45.x, w45.y, w67.x, w67.y};
#pragma unroll
        for (int i = 0; i < 8; i++) {
            acc[i][0] = fma2(w[i], xa.x, acc[i][0]);
            acc[i][1] = fma2(w[i], xa.y, acc[i][1]);
            acc[i][2] = fma2(w[i], xb.x, acc[i][2]);
            acc[i][3] = fma2(w[i], xb.y, acc[i][3]);
        }
    }

#pragma unroll
    for (int i = 0; i < 8; i++) {
        int r = r0 + i;
        if (r < RANK) {
            float* o = g_bufA + (size_t)r * NVOX + vbase + v0;
            *(ulonglong2*)(o)       = make_ulonglong2(acc[i][0], acc[i][1]);
            *(ulonglong2*)(o + 128) = make_ulonglong2(acc[i][2], acc[i][3]);
        }
    }
}

// ---------- Kernel 2: fused H+W 3-tap separable conv, smem tiled ----------
__global__ __launch_bounds__(256)
void k_convHW(const float* __restrict__ in, float* __restrict__ out,
              const float* __restrict__ Ukh, const float* __restrict__ Ukw) {
    __shared__ float s[(TH + 2) * (TW + 2) * DIM];   // 22.4 KB

    int r  = blockIdx.z;
    int h0 = blockIdx.y * TH;
    int w0 = blockIdx.x * TW;
    const float* base = in + (size_t)r * NVOX;

    const int NLOAD4 = (TH + 2) * (TW + 2) * (DIM / 4);
    for (int i = threadIdx.x; i < NLOAD4; i += 256) {
        int dq = i % (DIM / 4);
        int t  = i / (DIM / 4);
        int lw = t % (TW + 2);
        int lh = t / (TW + 2);
        int gh = h0 + lh - 1, gw = w0 + lw - 1;
        float4 val = make_float4(0.f, 0.f, 0.f, 0.f);
        if (gh >= 0 && gh < DIM && gw >= 0 && gw < DIM)
            val = *(const float4*)(base + gh * STRH + gw * STRW + dq * 4);
        *(float4*)(s + (lh * (TW + 2) + lw) * DIM + dq * 4) = val;
    }
    __syncthreads();

    float kh[3] = {Ukh[r], Ukh[RANK + r], Ukh[2 * RANK + r]};
    float kw[3] = {Ukw[r], Ukw[RANK + r], Ukw[2 * RANK + r]};
    float kk[9];
#pragma unroll
    for (int i = 0; i < 3; i++)
#pragma unroll
        for (int j = 0; j < 3; j++) kk[i * 3 + j] = kh[i] * kw[j];

    float* obase = out + (size_t)r * NVOX;
    const int NOUT4 = TH * TW * (DIM / 4);
    for (int o = threadIdx.x; o < NOUT4; o += 256) {
        int dq = o % (DIM / 4);
        int t  = o / (DIM / 4);
        int lw = t % TW;
        int lh = t / TW;
        float4 acc = make_float4(0.f, 0.f, 0.f, 0.f);
#pragma unroll
        for (int i = 0; i < 3; i++)
#pragma unroll
            for (int j = 0; j < 3; j++) {
                const float4 v = *(const float4*)(s + ((lh + i) * (TW + 2) + (lw + j)) * DIM + dq * 4);
                float c = kk[i * 3 + j];
                acc.x += c * v.x; acc.y += c * v.y;
                acc.z += c * v.z; acc.w += c * v.w;
            }
        *(float4*)(obase + (h0 + lh) * STRH + (w0 + lw) * STRW + dq * 4) = acc;
    }
}

// ---------- Kernel 3: depth conv + projection RANK -> 64 + bias ----------
// Dynamic smem layout (bytes):
//   t_s  float[53][256]   [0, 54272)
//   w_s  u64  [53][64]    [54272, 81408)
//   kd_s float[3][53]     [81408, 82044)
//   b_s  float[64]        [82044, 82300)
#define DPROJ_SMEM 82304
__global__ __launch_bounds__(256, 2)
void k_dproj(const float* __restrict__ in, const float* __restrict__ Ukd,
             const float* __restrict__ Ucout, const float* __restrict__ bias,
             float* __restrict__ out) {
    extern __shared__ char dsm[];
    float* t_s = (float*)dsm;
    unsigned long long* w_s = (unsigned long long*)(dsm + 54272);
    float* kd_s = (float*)(dsm + 81408);
    float* b_s  = (float*)(dsm + 82044);

    const int tid = threadIdx.x;
    const int vbase = blockIdx.x * VOXT;

    for (int i = tid; i < RANK * COUT; i += 256) {
        float v = Ucout[i];
        w_s[i] = pk2(v, v);
    }
    for (int i = tid; i < 3 * RANK; i += 256) kd_s[i] = Ukd[i];
    if (tid < COUT) b_s[tid] = bias[tid];
    __syncthreads();

    // stage 1: depth conv -> t_s[r][0..255]
    for (int i = tid; i < RANK * (VOXT / 4); i += 256) {
        int r = i >> 6, q = i & 63;
        int v4 = vbase + q * 4;
        int z  = v4 % DIM;                 // multiple of 4
        const float* p = in + (size_t)r * NVOX + v4;
        float4 c = *(const float4*)p;
        float lf = (z > 0)  ? p[-1] : 0.f;
        float rt = (z < 52) ? p[4]  : 0.f;
        float k0 = kd_s[r], k1 = kd_s[RANK + r], k2 = kd_s[2 * RANK + r];
        float4 t;
        t.x = k0 * lf  + k1 * c.x + k2 * c.y;
        t.y = k0 * c.x + k1 * c.y + k2 * c.z;
        t.z = k0 * c.y + k1 * c.z + k2 * c.w;
        t.w = k0 * c.z + k1 * c.w + k2 * rt;
        *(float4*)(t_s + r * VOXT + q * 4) = t;
    }
    __syncthreads();

    // stage 2: warp w -> couts [8w,8w+8); lane -> voxels lane*4 and lane*4+128.
    const int warp = tid >> 5;
    const int lane = tid & 31;
    const int j0 = warp * 8;
    const int v0 = lane * 4;

    unsigned long long acc[8][4];
#pragma unroll
    for (int i = 0; i < 8; i++)
#pragma unroll
        for (int k = 0; k < 4; k++) acc[i][k] = 0ull;

#pragma unroll 2
    for (int r = 0; r < RANK; r++) {
        const unsigned long long* wp = w_s + r * COUT + j0;
        ulonglong2 w01 = *(const ulonglong2*)(wp);
        ulonglong2 w23 = *(const ulonglong2*)(wp + 2);
        ulonglong2 w45 = *(const ulonglong2*)(wp + 4);
        ulonglong2 w67 = *(const ulonglong2*)(wp + 6);
        ulonglong2 ta  = *(const ulonglong2*)(t_s + r * VOXT + v0);
        ulonglong2 tb  = *(const ulonglong2*)(t_s + r * VOXT + v0 + 128);
        unsigned long long w[8] = {w01.x, w01.y, w23.x, w23.y, w45.x, w45.y, w67.x, w67.y};
#pragma unroll
        for (int i = 0; i < 8; i++) {
            acc[i][0] = fma2(w[i], ta.x, acc[i][0]);
            acc[i][1] = fma2(w[i], ta.y, acc[i][1]);
            acc[i][2] = fma2(w[i], tb.x, acc[i][2]);
            acc[i][3] = fma2(w[i], tb.y, acc[i][3]);
        }
    }

    const unsigned long long one2 = pk2(1.f, 1.f);
#pragma unroll
    for (int i = 0; i < 8; i++) {
        int j = j0 + i;
        unsigned long long bb = pk2(b_s[j], b_s[j]);
#pragma unroll
        for (int k = 0; k < 4; k++) acc[i][k] = fma2(bb, one2, acc[i][k]);
        float* o = out + (size_t)j * NVOX + vbase + v0;
        *(ulonglong2*)(o)       = make_ulonglong2(acc[i][0], acc[i][1]);
        *(ulonglong2*)(o + 128) = make_ulonglong2(acc[i][2], acc[i][3]);
    }
}

extern "C" void kernel_launch(void* const* d_in, const int* in_sizes, int n_in,
                              void* d_out, int out_size) {
    const float* x     = (const float*)d_in[0];
    const float* Ukh   = (const float*)d_in[1];
    const float* Ukw   = (const float*)d_in[2];
    const float* Ukd   = (const float*)d_in[3];
    const float* Ucin  = (const float*)d_in[4];
    const float* Ucout = (const float*)d_in[5];
    const float* bias  = (const float*)d_in[6];
    float* out = (float*)d_out;

    float *bufA, *bufB;
    cudaGetSymbolAddress((void**)&bufA, g_bufA);
    cudaGetSymbolAddress((void**)&bufB, g_bufB);

    cudaFuncSetAttribute(k_dproj, cudaFuncAttributeMaxDynamicSharedMemorySize, DPROJ_SMEM);

    const int gemm_blocks = NVOX / VOXT;   // 686

    k_pointwise<<<gemm_blocks, 224>>>(x, Ucin);
    dim3 g2(DIM / TW, DIM / TH, RANK);     // 7 x 7 x 53
    k_convHW<<<g2, 256>>>(bufA, bufB, Ukh, Ukw);
    k_dproj<<<gemm_blocks, 256, DPROJ_SMEM>>>(bufB, Ukd, Ucout, bias, out);
}

// round 6
// speedup vs baseline: 1.0150x; 1.0150x over previous
#include <cuda_runtime.h>

#define RANK 53
#define RPAD 56           // rank padded to 7 warps * 8
#define CIN  32
#define COUT 64
#define DIM  56
#define NVOX (56*56*56)   // 175616
#define STRH (56*56)
#define STRW 56
#define TH 8
#define TW 8
#define VOXT 256          // voxels per GEMM tile (NVOX/VOXT = 686 exact)

// Scratch: two rank-major intermediates [RANK][NVOX] (~37 MB each).
__device__ float g_bufA[RANK * NVOX];
__device__ float g_bufB[RANK * NVOX];

// ---------- packed f32x2 helpers (sm_103a) ----------
__device__ __forceinline__ unsigned long long pk2(float lo, float hi) {
    unsigned long long r;
    asm("mov.b64 %0, {%1, %2};" : "=l"(r) : "f"(lo), "f"(hi));
    return r;
}
__device__ __forceinline__ unsigned long long fma2(unsigned long long a,
                                                   unsigned long long b,
                                                   unsigned long long c) {
    unsigned long long d;
    asm("fma.rn.f32x2 %0, %1, %2, %3;" : "=l"(d) : "l"(a), "l"(b), "l"(c));
    return d;
}

// ---------- Kernel 1: pointwise Cin -> RANK ----------
// Warp w -> ranks [8w,8w+8) (weights warp-uniform -> broadcast LDS, 1 cyc each).
// Lane owns voxels {lane*4..+3} and {lane*4+128..+3} (conflict-free LDS.128).
// Inner c-iter: 6 LDS.128 (12 crossbar cyc) : 32 FFMA2 (16 fma-pipe cyc) -> fma binds.
__global__ __launch_bounds__(224, 3)
void k_pointwise(const float* __restrict__ x, const float* __restrict__ Ucin) {
    __shared__ float x_s[CIN * VOXT];                    // 32 KB
    __shared__ unsigned long long w_s[CIN * RPAD];       // 14 KB

    const int tid = threadIdx.x;
    const int vbase = blockIdx.x * VOXT;

    for (int i = tid; i < CIN * RPAD; i += 224) {
        int c = i / RPAD, r = i % RPAD;
        float v = (r < RANK) ? Ucin[c * RANK + r] : 0.f;
        w_s[i] = pk2(v, v);
    }
    for (int i = tid; i < CIN * (VOXT / 4); i += 224) {
        int c = i >> 6, q = i & 63;
        *(float4*)(x_s + c * VOXT + q * 4) =
            *(const float4*)(x + (size_t)c * NVOX + vbase + q * 4);
    }
    __syncthreads();

    const int warp = tid >> 5;
    const int lane = tid & 31;
    const int r0 = warp * 8;
    const int v0 = lane * 4;

    unsigned long long acc[8][4];
#pragma unroll
    for (int i = 0; i < 8; i++)
#pragma unroll
        for (int k = 0; k < 4; k++) acc[i][k] = 0ull;

    const unsigned long long* wp = w_s + r0;
    const float* xp = x_s + v0;
    for (int c = 0; c < CIN; c++, wp += RPAD, xp += VOXT) {
        ulonglong2 w01 = *(const ulonglong2*)(wp);
        ulonglong2 w23 = *(const ulonglong2*)(wp + 2);
        ulonglong2 w45 = *(const ulonglong2*)(wp + 4);
        ulonglong2 w67 = *(const ulonglong2*)(wp + 6);
        ulonglong2 xa  = *(const ulonglong2*)(xp);
        ulonglong2 xb  = *(const ulonglong2*)(xp + 128);
        acc[0][0] = fma2(w01.x, xa.x, acc[0][0]);
        acc[0][1] = fma2(w01.x, xa.y, acc[0][1]);
        acc[0][2] = fma2(w01.x, xb.x, acc[0][2]);
        acc[0][3] = fma2(w01.x, xb.y, acc[0][3]);
        acc[1][0] = fma2(w01.y, xa.x, acc[1][0]);
        acc[1][1] = fma2(w01.y, xa.y, acc[1][1]);
        acc[1][2] = fma2(w01.y, xb.x, acc[1][2]);
        acc[1][3] = fma2(w01.y, xb.y, acc[1][3]);
        acc[2][0] = fma2(w23.x, xa.x, acc[2][0]);
        acc[2][1] = fma2(w23.x, xa.y, acc[2][1]);
        acc[2][2] = fma2(w23.x, xb.x, acc[2][2]);
        acc[2][3] = fma2(w23.x, xb.y, acc[2][3]);
        acc[3][0] = fma2(w23.y, xa.x, acc[3][0]);
        acc[3][1] = fma2(w23.y, xa.y, acc[3][1]);
        acc[3][2] = fma2(w23.y, xb.x, acc[3][2]);
        acc[3][3] = fma2(w23.y, xb.y, acc[3][3]);
        acc[4][0] = fma2(w45.x, xa.x, acc[4][0]);
        acc[4][1] = fma2(w45.x, xa.y, acc[4][1]);
        acc[4][2] = fma2(w45.x, xb.x, acc[4][2]);
        acc[4][3] = fma2(w45.x, xb.y, acc[4][3]);
        acc[5][0] = fma2(w45.y, xa.x, acc[5][0]);
        acc[5][1] = fma2(w45.y, xa.y, acc[5][1]);
        acc[5][2] = fma2(w45.y, xb.x, acc[5][2]);
        acc[5][3] = fma2(w45.y, xb.y, acc[5][3]);
        acc[6][0] = fma2(w67.x, xa.x, acc[6][0]);
        acc[6][1] = fma2(w67.x, xa.y, acc[6][1]);
        acc[6][2] = fma2(w67.x, xb.x, acc[6][2]);
        acc[6][3] = fma2(w67.x, xb.y, acc[6][3]);
        acc[7][0] = fma2(w67.y, xa.x, acc[7][0]);
        acc[7][1] = fma2(w67.y, xa.y, acc[7][1]);
        acc[7][2] = fma2(w67.y, xb.x, acc[7][2]);
        acc[7][3] = fma2(w67.y, xb.y, acc[7][3]);
    }

#pragma unroll
    for (int i = 0; i < 8; i++) {
        int r = r0 + i;
        if (r < RANK) {
            float* o = g_bufA + (size_t)r * NVOX + vbase + v0;
            *(ulonglong2*)(o)       = make_ulonglong2(acc[i][0], acc[i][1]);
            *(ulonglong2*)(o + 128) = make_ulonglong2(acc[i][2], acc[i][3]);
        }
    }
}

// ---------- Kernel 2: fused H+W 3-tap separable conv, smem tiled ----------
__global__ __launch_bounds__(256)
void k_convHW(const float* __restrict__ in, float* __restrict__ out,
              const float* __restrict__ Ukh, const float* __restrict__ Ukw) {
    __shared__ float s[(TH + 2) * (TW + 2) * DIM];   // 22.4 KB

    int r  = blockIdx.z;
    int h0 = blockIdx.y * TH;
    int w0 = blockIdx.x * TW;
    const float* base = in + (size_t)r * NVOX;

    const int NLOAD4 = (TH + 2) * (TW + 2) * (DIM / 4);
    for (int i = threadIdx.x; i < NLOAD4; i += 256) {
        int dq = i % (DIM / 4);
        int t  = i / (DIM / 4);
        int lw = t % (TW + 2);
        int lh = t / (TW + 2);
        int gh = h0 + lh - 1, gw = w0 + lw - 1;
        float4 val = make_float4(0.f, 0.f, 0.f, 0.f);
        if (gh >= 0 && gh < DIM && gw >= 0 && gw < DIM)
            val = *(const float4*)(base + gh * STRH + gw * STRW + dq * 4);
        *(float4*)(s + (lh * (TW + 2) + lw) * DIM + dq * 4) = val;
    }
    __syncthreads();

    float kh[3] = {Ukh[r], Ukh[RANK + r], Ukh[2 * RANK + r]};
    float kw[3] = {Ukw[r], Ukw[RANK + r], Ukw[2 * RANK + r]};
    float kk[9];
#pragma unroll
    for (int i = 0; i < 3; i++)
#pragma unroll
        for (int j = 0; j < 3; j++) kk[i * 3 + j] = kh[i] * kw[j];

    float* obase = out + (size_t)r * NVOX;
    const int NOUT4 = TH * TW * (DIM / 4);
    for (int o = threadIdx.x; o < NOUT4; o += 256) {
        int dq = o % (DIM / 4);
        int t  = o / (DIM / 4);
        int lw = t % TW;
        int lh = t / TW;
        float4 acc = make_float4(0.f, 0.f, 0.f, 0.f);
#pragma unroll
        for (int i = 0; i < 3; i++)
#pragma unroll
            for (int j = 0; j < 3; j++) {
                const float4 v = *(const float4*)(s + ((lh + i) * (TW + 2) + (lw + j)) * DIM + dq * 4);
                float c = kk[i * 3 + j];
                acc.x += c * v.x; acc.y += c * v.y;
                acc.z += c * v.z; acc.w += c * v.w;
            }
        *(float4*)(obase + (h0 + lh) * STRH + (w0 + lw) * STRW + dq * 4) = acc;
    }
}

// ---------- Kernel 3: depth conv + projection RANK -> 64 + bias ----------
// Dynamic smem layout (bytes):
//   t_s  float[53][256]   [0, 54272)
//   w_s  u64  [53][64]    [54272, 81408)
//   kd_s float[3][53]     [81408, 82044)
//   b_s  float[64]        [82044, 82300)
#define DPROJ_SMEM 82304
__global__ __launch_bounds__(256, 2)
void k_dproj(const float* __restrict__ in, const float* __restrict__ Ukd,
             const float* __restrict__ Ucout, const float* __restrict__ bias,
             float* __restrict__ out) {
    extern __shared__ char dsm[];
    float* t_s = (float*)dsm;
    unsigned long long* w_s = (unsigned long long*)(dsm + 54272);
    float* kd_s = (float*)(dsm + 81408);
    float* b_s  = (float*)(dsm + 82044);

    const int tid = threadIdx.x;
    const int vbase = blockIdx.x * VOXT;

    for (int i = tid; i < RANK * COUT; i += 256) {
        float v = Ucout[i];
        w_s[i] = pk2(v, v);
    }
    for (int i = tid; i < 3 * RANK; i += 256) kd_s[i] = Ukd[i];
    if (tid < COUT) b_s[tid] = bias[tid];
    __syncthreads();

    // stage 1: depth conv -> t_s[r][0..255]
    for (int i = tid; i < RANK * (VOXT / 4); i += 256) {
        int r = i >> 6, q = i & 63;
        int v4 = vbase + q * 4;
        int z  = v4 % DIM;
        const float* p = in + (size_t)r * NVOX + v4;
        float4 c = *(const float4*)p;
        float lf = (z > 0)  ? p[-1] : 0.f;
        float rt = (z < 52) ? p[4]  : 0.f;
        float k0 = kd_s[r], k1 = kd_s[RANK + r], k2 = kd_s[2 * RANK + r];
        float4 t;
        t.x = k0 * lf  + k1 * c.x + k2 * c.y;
        t.y = k0 * c.x + k1 * c.y + k2 * c.z;
        t.z = k0 * c.y + k1 * c.z + k2 * c.w;
        t.w = k0 * c.z + k1 * c.w + k2 * rt;
        *(float4*)(t_s + r * VOXT + q * 4) = t;
    }
    __syncthreads();

    // stage 2: warp w -> couts [8w,8w+8); lane -> voxels lane*4 and lane*4+128.
    const int warp = tid >> 5;
    const int lane = tid & 31;
    const int j0 = warp * 8;
    const int v0 = lane * 4;

    unsigned long long acc[8][4];
#pragma unroll
    for (int i = 0; i < 8; i++)
#pragma unroll
        for (int k = 0; k < 4; k++) acc[i][k] = 0ull;

    const unsigned long long* wp = w_s + j0;
    const float* tp = t_s + v0;
    for (int r = 0; r < RANK; r++, wp += COUT, tp += VOXT) {
        ulonglong2 w01 = *(const ulonglong2*)(wp);
        ulonglong2 w23 = *(const ulonglong2*)(wp + 2);
        ulonglong2 w45 = *(const ulonglong2*)(wp + 4);
        ulonglong2 w67 = *(const ulonglong2*)(wp + 6);
        ulonglong2 ta  = *(const ulonglong2*)(tp);
        ulonglong2 tb  = *(const ulonglong2*)(tp + 128);
        unsigned long long w[8] = {w01.x, w01.y, w23.x, w23.y, w45.x, w45.y, w67.x, w67.y};
#pragma unroll
        for (int i = 0; i < 8; i++) {
            acc[i][0] = fma2(w[i], ta.x, acc[i][0]);
            acc[i][1] = fma2(w[i], ta.y, acc[i][1]);
            acc[i][2] = fma2(w[i], tb.x, acc[i][2]);
            acc[i][3] = fma2(w[i], tb.y, acc[i][3]);
        }
    }

    const unsigned long long one2 = pk2(1.f, 1.f);
#pragma unroll
    for (int i = 0; i < 8; i++) {
        int j = j0 + i;
        unsigned long long bb = pk2(b_s[j], b_s[j]);
#pragma unroll
        for (int k = 0; k < 4; k++) acc[i][k] = fma2(bb, one2, acc[i][k]);
        float* o = out + (size_t)j * NVOX + vbase + v0;
        *(ulonglong2*)(o)       = make_ulonglong2(acc[i][0], acc[i][1]);
        *(ulonglong2*)(o + 128) = make_ulonglong2(acc[i][2], acc[i][3]);
    }
}

extern "C" void kernel_launch(void* const* d_in, const int* in_sizes, int n_in,
                              void* d_out, int out_size) {
    const float* x     = (const float*)d_in[0];
    const float* Ukh   = (const float*)d_in[1];
    const float* Ukw   = (const float*)d_in[2];
    const float* Ukd   = (const float*)d_in[3];
    const float* Ucin  = (const float*)d_in[4];
    const float* Ucout = (const float*)d_in[5];
    const float* bias  = (const float*)d_in[6];
    float* out = (float*)d_out;

    float *bufA, *bufB;
    cudaGetSymbolAddress((void**)&bufA, g_bufA);
    cudaGetSymbolAddress((void**)&bufB, g_bufB);

    cudaFuncSetAttribute(k_dproj, cudaFuncAttributeMaxDynamicSharedMemorySize, DPROJ_SMEM);

    const int gemm_blocks = NVOX / VOXT;   // 686

    k_pointwise<<<gemm_blocks, 224>>>(x, Ucin);
    dim3 g2(DIM / TW, DIM / TH, RANK);     // 7 x 7 x 53
    k_convHW<<<g2, 256>>>(bufA, bufB, Ukh, Ukw);
    k_dproj<<<gemm_blocks, 256, DPROJ_SMEM>>>(bufB, Ukd, Ucout, bias, out);
}

// round 7
// speedup vs baseline: 1.2293x; 1.2112x over previous
#include <cuda_runtime.h>

#define RANK 53
#define RPAD 56
#define CIN  32
#define COUT 64
#define DIM  56
#define NVOX (56*56*56)   // 175616
#define STRH (56*56)
#define STRW 56
#define TH 8
#define TW 8
#define VOXT 128          // voxels per GEMM tile
#define NT   (NVOX / VOXT) // 1372 tiles

__device__ float g_bufA[RANK * NVOX];
__device__ float g_bufB[RANK * NVOX];

typedef unsigned long long ull;

__device__ __forceinline__ ull pk2(float lo, float hi) {
    ull r; asm("mov.b64 %0, {%1, %2};" : "=l"(r) : "f"(lo), "f"(hi)); return r;
}
__device__ __forceinline__ ull fma2(ull a, ull b, ull c) {
    ull d; asm("fma.rn.f32x2 %0, %1, %2, %3;" : "=l"(d) : "l"(a), "l"(b), "l"(c)); return d;
}
__device__ __forceinline__ void cpa16(float* smem_dst, const float* gsrc) {
    unsigned s = (unsigned)__cvta_generic_to_shared(smem_dst);
    asm volatile("cp.async.cg.shared.global [%0], [%1], 16;" :: "r"(s), "l"(gsrc));
}
#define CPA_COMMIT() asm volatile("cp.async.commit_group;" ::: "memory")
#define CPA_WAIT1()  asm volatile("cp.async.wait_group 1;"  ::: "memory")

// ---------- Kernel 1: pointwise Cin -> RANK (persistent, cp.async 2-buffer) ----------
// Warp w -> ranks [8w,8w+8) (broadcast weight LDS); lane -> 4 voxels.
__global__ __launch_bounds__(224, 4)
void k_pointwise(const float* __restrict__ x, const float* __restrict__ Ucin) {
    __shared__ ull   w_s[CIN * RPAD];        // 14 KB
    __shared__ float x_s[2][CIN * VOXT];     // 2 x 16 KB

    const int tid = threadIdx.x;
    const int GRID = gridDim.x;

    // prefetch tile t0 into buf0 first (overlaps with weight staging)
    int t = blockIdx.x;
    if (t < NT)
        for (int i = tid; i < CIN * 32; i += 224) {
            int c = i >> 5, q = i & 31;
            cpa16(x_s[0] + c * VOXT + q * 4, x + (size_t)c * NVOX + t * VOXT + q * 4);
        }
    CPA_COMMIT();

    for (int i = tid; i < CIN * RPAD; i += 224) {
        int c = i / RPAD, r = i % RPAD;
        float v = (r < RANK) ? Ucin[c * RANK + r] : 0.f;
        w_s[i] = pk2(v, v);
    }

    if (t + GRID < NT)
        for (int i = tid; i < CIN * 32; i += 224) {
            int c = i >> 5, q = i & 31;
            cpa16(x_s[1] + c * VOXT + q * 4, x + (size_t)c * NVOX + (t + GRID) * VOXT + q * 4);
        }
    CPA_COMMIT();

    const int warp = tid >> 5;
    const int lane = tid & 31;
    const int r0 = warp * 8;
    const int v0 = lane * 4;

    int p = 0;
    for (; t < NT; t += GRID, p ^= 1) {
        CPA_WAIT1();
        __syncthreads();
        const float* xs = x_s[p];

        ull acc[8][2];
#pragma unroll
        for (int i = 0; i < 8; i++) { acc[i][0] = 0ull; acc[i][1] = 0ull; }

        const ull* wp = w_s + r0;
        const float* xp = xs + v0;
        for (int c = 0; c < CIN; c++, wp += RPAD, xp += VOXT) {
            ulonglong2 w01 = *(const ulonglong2*)(wp);
            ulonglong2 w23 = *(const ulonglong2*)(wp + 2);
            ulonglong2 w45 = *(const ulonglong2*)(wp + 4);
            ulonglong2 w67 = *(const ulonglong2*)(wp + 6);
            ulonglong2 xa  = *(const ulonglong2*)(xp);
            ull w[8] = {w01.x, w01.y, w23.x, w23.y, w45.x, w45.y, w67.x, w67.y};
#pragma unroll
            for (int i = 0; i < 8; i++) {
                acc[i][0] = fma2(w[i], xa.x, acc[i][0]);
                acc[i][1] = fma2(w[i], xa.y, acc[i][1]);
            }
        }

#pragma unroll
        for (int i = 0; i < 8; i++) {
            int r = r0 + i;
            if (r < RANK)
                *(ulonglong2*)(g_bufA + (size_t)r * NVOX + t * VOXT + v0) =
                    make_ulonglong2(acc[i][0], acc[i][1]);
        }
        __syncthreads();   // all reads of x_s[p] done before refill

        int tn = t + 2 * GRID;
        if (tn < NT)
            for (int i = tid; i < CIN * 32; i += 224) {
                int c = i >> 5, q = i & 31;
                cpa16(x_s[p] + c * VOXT + q * 4, x + (size_t)c * NVOX + tn * VOXT + q * 4);
            }
        CPA_COMMIT();      // commit (possibly empty) to keep group accounting
    }
}

// ---------- Kernel 2: fused H+W 3-tap separable conv, smem tiled ----------
__global__ __launch_bounds__(256)
void k_convHW(const float* __restrict__ in, float* __restrict__ out,
              const float* __restrict__ Ukh, const float* __restrict__ Ukw) {
    __shared__ float s[(TH + 2) * (TW + 2) * DIM];   // 22.4 KB

    int r  = blockIdx.z;
    int h0 = blockIdx.y * TH;
    int w0 = blockIdx.x * TW;
    const float* base = in + (size_t)r * NVOX;

    const int NLOAD4 = (TH + 2) * (TW + 2) * (DIM / 4);
    for (int i = threadIdx.x; i < NLOAD4; i += 256) {
        int dq = i % (DIM / 4);
        int t  = i / (DIM / 4);
        int lw = t % (TW + 2);
        int lh = t / (TW + 2);
        int gh = h0 + lh - 1, gw = w0 + lw - 1;
        float4 val = make_float4(0.f, 0.f, 0.f, 0.f);
        if (gh >= 0 && gh < DIM && gw >= 0 && gw < DIM)
            val = *(const float4*)(base + gh * STRH + gw * STRW + dq * 4);
        *(float4*)(s + (lh * (TW + 2) + lw) * DIM + dq * 4) = val;
    }
    __syncthreads();

    float kh[3] = {Ukh[r], Ukh[RANK + r], Ukh[2 * RANK + r]};
    float kw[3] = {Ukw[r], Ukw[RANK + r], Ukw[2 * RANK + r]};
    float kk[9];
#pragma unroll
    for (int i = 0; i < 3; i++)
#pragma unroll
        for (int j = 0; j < 3; j++) kk[i * 3 + j] = kh[i] * kw[j];

    float* obase = out + (size_t)r * NVOX;
    const int NOUT4 = TH * TW * (DIM / 4);
    for (int o = threadIdx.x; o < NOUT4; o += 256) {
        int dq = o % (DIM / 4);
        int t  = o / (DIM / 4);
        int lw = t % TW;
        int lh = t / TW;
        float4 acc = make_float4(0.f, 0.f, 0.f, 0.f);
#pragma unroll
        for (int i = 0; i < 3; i++)
#pragma unroll
            for (int j = 0; j < 3; j++) {
                const float4 v = *(const float4*)(s + ((lh + i) * (TW + 2) + (lw + j)) * DIM + dq * 4);
                float c = kk[i * 3 + j];
                acc.x += c * v.x; acc.y += c * v.y;
                acc.z += c * v.z; acc.w += c * v.w;
            }
        *(float4*)(obase + (h0 + lh) * STRH + (w0 + lw) * STRW + dq * 4) = acc;
    }
}

// ---------- Kernel 3: depth conv + projection RANK -> 64 + bias (persistent) ----------
// Dynamic smem layout (bytes):
//   t_s  float[53][128]  [0, 27136)
//   w_s  u64  [53][64]   [27136, 54272)
//   kd_s float[3][53]    [54272, 54908)
//   b_s  float[64]       [54908, 55164)
#define DPROJ_SMEM 55296
__global__ __launch_bounds__(256, 3)
void k_dproj(const float* __restrict__ in, const float* __restrict__ Ukd,
             const float* __restrict__ Ucout, const float* __restrict__ bias,
             float* __restrict__ out) {
    extern __shared__ char dsm[];
    float* t_s = (float*)dsm;
    ull*   w_s = (ull*)(dsm + 27136);
    float* kd_s = (float*)(dsm + 54272);
    float* b_s  = (float*)(dsm + 54908);

    const int tid = threadIdx.x;
    const int GRID = gridDim.x;

    for (int i = tid; i < RANK * COUT; i += 256) {
        float v = Ucout[i];
        w_s[i] = pk2(v, v);
    }
    for (int i = tid; i < 3 * RANK; i += 256) kd_s[i] = Ukd[i];
    if (tid < COUT) b_s[tid] = bias[tid];
    __syncthreads();

    const int warp = tid >> 5;
    const int lane = tid & 31;
    const int j0 = warp * 8;
    const int v0 = lane * 4;

    for (int t = blockIdx.x; t < NT; t += GRID) {
        const int vbase = t * VOXT;

        // stage 1: depth conv -> t_s[53][128]
        for (int i = tid; i < RANK * 32; i += 256) {
            int r = i >> 5, q = i & 31;
            int v4 = vbase + q * 4;
            int z  = v4 % DIM;
            const float* p = in + (size_t)r * NVOX + v4;
            float4 c = *(const float4*)p;
            float lf = (z > 0)  ? p[-1] : 0.f;
            float rt = (z < 52) ? p[4]  : 0.f;
            float k0 = kd_s[r], k1 = kd_s[RANK + r], k2 = kd_s[2 * RANK + r];
            float4 tt;
            tt.x = k0 * lf  + k1 * c.x + k2 * c.y;
            tt.y = k0 * c.x + k1 * c.y + k2 * c.z;
            tt.z = k0 * c.y + k1 * c.z + k2 * c.w;
            tt.w = k0 * c.z + k1 * c.w + k2 * rt;
            *(float4*)(t_s + r * VOXT + q * 4) = tt;
        }
        __syncthreads();

        // stage 2: out[64][128] = W^T * t
        ull acc[8][2];
#pragma unroll
        for (int i = 0; i < 8; i++) { acc[i][0] = 0ull; acc[i][1] = 0ull; }

        const ull* wp = w_s + j0;
        const float* tp = t_s + v0;
        for (int r = 0; r < RANK; r++, wp += COUT, tp += VOXT) {
            ulonglong2 w01 = *(const ulonglong2*)(wp);
            ulonglong2 w23 = *(const ulonglong2*)(wp + 2);
            ulonglong2 w45 = *(const ulonglong2*)(wp + 4);
            ulonglong2 w67 = *(const ulonglong2*)(wp + 6);
            ulonglong2 ta  = *(const ulonglong2*)(tp);
            ull w[8] = {w01.x, w01.y, w23.x, w23.y, w45.x, w45.y, w67.x, w67.y};
#pragma unroll
            for (int i = 0; i < 8; i++) {
                acc[i][0] = fma2(w[i], ta.x, acc[i][0]);
                acc[i][1] = fma2(w[i], ta.y, acc[i][1]);
            }
        }

        const ull one2 = pk2(1.f, 1.f);
#pragma unroll
        for (int i = 0; i < 8; i++) {
            int j = j0 + i;
            ull bb = pk2(b_s[j], b_s[j]);
            acc[i][0] = fma2(bb, one2, acc[i][0]);
            acc[i][1] = fma2(bb, one2, acc[i][1]);
            *(ulonglong2*)(out + (size_t)j * NVOX + vbase + v0) =
                make_ulonglong2(acc[i][0], acc[i][1]);
        }
        __syncthreads();   // done reading t_s before next tile overwrites
    }
}

extern "C" void kernel_launch(void* const* d_in, const int* in_sizes, int n_in,
                              void* d_out, int out_size) {
    const float* x     = (const float*)d_in[0];
    const float* Ukh   = (const float*)d_in[1];
    const float* Ukw   = (const float*)d_in[2];
    const float* Ukd   = (const float*)d_in[3];
    const float* Ucin  = (const float*)d_in[4];
    const float* Ucout = (const float*)d_in[5];
    const float* bias  = (const float*)d_in[6];
    float* out = (float*)d_out;

    float *bufA, *bufB;
    cudaGetSymbolAddress((void**)&bufA, g_bufA);
    cudaGetSymbolAddress((void**)&bufB, g_bufB);

    cudaFuncSetAttribute(k_dproj, cudaFuncAttributeMaxDynamicSharedMemorySize, DPROJ_SMEM);

    // one full wave each: 148 SMs x 4 CTAs / x 3 CTAs
    k_pointwise<<<592, 224>>>(x, Ucin);
    dim3 g2(DIM / TW, DIM / TH, RANK);     // 7 x 7 x 53
    k_convHW<<<g2, 256>>>(bufA, bufB, Ukh, Ukw);
    k_dproj<<<444, 256, DPROJ_SMEM>>>(bufB, Ukd, Ucout, bias, out);
}

// round 8
// speedup vs baseline: 1.2350x; 1.0046x over previous
#include <cuda_runtime.h>

#define RANK 53
#define RPAD 56
#define CIN  32
#define COUT 64
#define DIM  56
#define NVOX (56*56*56)   // 175616
#define STRH (56*56)
#define STRW 56
#define TH 8
#define TW 8
#define VOXT 256          // voxels per GEMM tile
#define NT   (NVOX / VOXT) // 686

__device__ float g_bufA[RANK * NVOX];
__device__ float g_bufB[RANK * NVOX];

typedef unsigned long long ull;

__device__ __forceinline__ ull pk2(float lo, float hi) {
    ull r; asm("mov.b64 %0, {%1, %2};" : "=l"(r) : "f"(lo), "f"(hi)); return r;
}
__device__ __forceinline__ ull fma2(ull a, ull b, ull c) {
    ull d; asm("fma.rn.f32x2 %0, %1, %2, %3;" : "=l"(d) : "l"(a), "l"(b), "l"(c)); return d;
}
__device__ __forceinline__ void cpa16(float* smem_dst, const float* gsrc) {
    unsigned s = (unsigned)__cvta_generic_to_shared(smem_dst);
    asm volatile("cp.async.cg.shared.global [%0], [%1], 16;" :: "r"(s), "l"(gsrc));
}
#define CPA_COMMIT() asm volatile("cp.async.commit_group;" ::: "memory")
#define CPA_WAIT1()  asm volatile("cp.async.wait_group 1;"  ::: "memory")

// ---------- Kernel 1: pointwise Cin -> RANK (persistent, cp.async, 8x8 tile) ----------
// Dynamic smem: x_s[2][CIN*VOXT] floats [0,65536); w_s ull[CIN*RPAD] [65536,79872)
#define PW_SMEM 79872
__global__ __launch_bounds__(224, 2)
void k_pointwise(const float* __restrict__ x, const float* __restrict__ Ucin) {
    extern __shared__ char psm[];
    float* x_s[2] = {(float*)psm, (float*)(psm + CIN * VOXT * 4)};
    ull*   w_s    = (ull*)(psm + 65536);

    const int tid = threadIdx.x;
    const int GRID = gridDim.x;

    int t = blockIdx.x;
    if (t < NT)
        for (int i = tid; i < CIN * (VOXT / 4); i += 224) {
            int c = i >> 6, q = i & 63;
            cpa16(x_s[0] + c * VOXT + q * 4, x + (size_t)c * NVOX + t * VOXT + q * 4);
        }
    CPA_COMMIT();

    for (int i = tid; i < CIN * RPAD; i += 224) {
        int c = i / RPAD, r = i % RPAD;
        float v = (r < RANK) ? Ucin[c * RANK + r] : 0.f;
        w_s[i] = pk2(v, v);
    }

    if (t + GRID < NT)
        for (int i = tid; i < CIN * (VOXT / 4); i += 224) {
            int c = i >> 6, q = i & 63;
            cpa16(x_s[1] + c * VOXT + q * 4, x + (size_t)c * NVOX + (t + GRID) * VOXT + q * 4);
        }
    CPA_COMMIT();

    const int warp = tid >> 5;
    const int lane = tid & 31;
    const int r0 = warp * 8;
    const int v0 = lane * 4;

    int p = 0;
    for (; t < NT; t += GRID, p ^= 1) {
        CPA_WAIT1();
        __syncthreads();
        const float* xs = x_s[p];

        ull acc[8][4];
#pragma unroll
        for (int i = 0; i < 8; i++)
#pragma unroll
            for (int k = 0; k < 4; k++) acc[i][k] = 0ull;

        const ull* wp = w_s + r0;
        const float* xp = xs + v0;
        for (int c = 0; c < CIN; c++, wp += RPAD, xp += VOXT) {
            ulonglong2 w01 = *(const ulonglong2*)(wp);
            ulonglong2 w23 = *(const ulonglong2*)(wp + 2);
            ulonglong2 w45 = *(const ulonglong2*)(wp + 4);
            ulonglong2 w67 = *(const ulonglong2*)(wp + 6);
            ulonglong2 xa  = *(const ulonglong2*)(xp);
            ulonglong2 xb  = *(const ulonglong2*)(xp + 128);
            ull w[8] = {w01.x, w01.y, w23.x, w23.y, w45.x, w45.y, w67.x, w67.y};
#pragma unroll
            for (int i = 0; i < 8; i++) {
                acc[i][0] = fma2(w[i], xa.x, acc[i][0]);
                acc[i][1] = fma2(w[i], xa.y, acc[i][1]);
                acc[i][2] = fma2(w[i], xb.x, acc[i][2]);
                acc[i][3] = fma2(w[i], xb.y, acc[i][3]);
            }
        }

#pragma unroll
        for (int i = 0; i < 8; i++) {
            int r = r0 + i;
            if (r < RANK) {
                float* o = g_bufA + (size_t)r * NVOX + t * VOXT + v0;
                *(ulonglong2*)(o)       = make_ulonglong2(acc[i][0], acc[i][1]);
                *(ulonglong2*)(o + 128) = make_ulonglong2(acc[i][2], acc[i][3]);
            }
        }
        __syncthreads();

        int tn = t + 2 * GRID;
        if (tn < NT)
            for (int i = tid; i < CIN * (VOXT / 4); i += 224) {
                int c = i >> 6, q = i & 63;
                cpa16(x_s[p] + c * VOXT + q * 4, x + (size_t)c * NVOX + tn * VOXT + q * 4);
            }
        CPA_COMMIT();
    }
}

// ---------- Kernel 2: fused H+W 3-tap separable conv, smem tiled ----------
__global__ __launch_bounds__(256)
void k_convHW(const float* __restrict__ in, float* __restrict__ out,
              const float* __restrict__ Ukh, const float* __restrict__ Ukw) {
    __shared__ float s[(TH + 2) * (TW + 2) * DIM];   // 22.4 KB

    int r  = blockIdx.z;
    int h0 = blockIdx.y * TH;
    int w0 = blockIdx.x * TW;
    const float* base = in + (size_t)r * NVOX;

    const int NLOAD4 = (TH + 2) * (TW + 2) * (DIM / 4);
    for (int i = threadIdx.x; i < NLOAD4; i += 256) {
        int dq = i % (DIM / 4);
        int t  = i / (DIM / 4);
        int lw = t % (TW + 2);
        int lh = t / (TW + 2);
        int gh = h0 + lh - 1, gw = w0 + lw - 1;
        float4 val = make_float4(0.f, 0.f, 0.f, 0.f);
        if (gh >= 0 && gh < DIM && gw >= 0 && gw < DIM)
            val = *(const float4*)(base + gh * STRH + gw * STRW + dq * 4);
        *(float4*)(s + (lh * (TW + 2) + lw) * DIM + dq * 4) = val;
    }
    __syncthreads();

    float kh[3] = {Ukh[r], Ukh[RANK + r], Ukh[2 * RANK + r]};
    float kw[3] = {Ukw[r], Ukw[RANK + r], Ukw[2 * RANK + r]};
    float kk[9];
#pragma unroll
    for (int i = 0; i < 3; i++)
#pragma unroll
        for (int j = 0; j < 3; j++) kk[i * 3 + j] = kh[i] * kw[j];

    float* obase = out + (size_t)r * NVOX;
    const int NOUT4 = TH * TW * (DIM / 4);
    for (int o = threadIdx.x; o < NOUT4; o += 256) {
        int dq = o % (DIM / 4);
        int t  = o / (DIM / 4);
        int lw = t % TW;
        int lh = t / TW;
        float4 acc = make_float4(0.f, 0.f, 0.f, 0.f);
#pragma unroll
        for (int i = 0; i < 3; i++)
#pragma unroll
            for (int j = 0; j < 3; j++) {
                const float4 v = *(const float4*)(s + ((lh + i) * (TW + 2) + (lw + j)) * DIM + dq * 4);
                float c = kk[i * 3 + j];
                acc.x += c * v.x; acc.y += c * v.y;
                acc.z += c * v.z; acc.w += c * v.w;
            }
        *(float4*)(obase + (h0 + lh) * STRH + (w0 + lw) * STRW + dq * 4) = acc;
    }
}

// ---------- Kernel 3: depth conv + projection RANK -> 64 + bias (persistent, 8x8) ----------
// Dynamic smem layout (bytes):
//   t_s  float[53][256]  [0, 54272)
//   w_s  u64  [53][64]   [54272, 81408)
//   kd_s float[3][53]    [81408, 82044)
//   b_s  float[64]       [82044, 82300)
#define DPROJ_SMEM 82432
__global__ __launch_bounds__(256, 2)
void k_dproj(const float* __restrict__ in, const float* __restrict__ Ukd,
             const float* __restrict__ Ucout, const float* __restrict__ bias,
             float* __restrict__ out) {
    extern __shared__ char dsm[];
    float* t_s = (float*)dsm;
    ull*   w_s = (ull*)(dsm + 54272);
    float* kd_s = (float*)(dsm + 81408);
    float* b_s  = (float*)(dsm + 82044);

    const int tid = threadIdx.x;
    const int GRID = gridDim.x;

    for (int i = tid; i < RANK * COUT; i += 256) {
        float v = Ucout[i];
        w_s[i] = pk2(v, v);
    }
    for (int i = tid; i < 3 * RANK; i += 256) kd_s[i] = Ukd[i];
    if (tid < COUT) b_s[tid] = bias[tid];
    __syncthreads();

    const int warp = tid >> 5;
    const int lane = tid & 31;
    const int j0 = warp * 8;
    const int v0 = lane * 4;

    for (int t = blockIdx.x; t < NT; t += GRID) {
        const int vbase = t * VOXT;

        // stage 1: depth conv -> t_s[53][256]
        for (int i = tid; i < RANK * (VOXT / 4); i += 256) {
            int r = i >> 6, q = i & 63;
            int v4 = vbase + q * 4;
            int z  = v4 % DIM;
            const float* p = in + (size_t)r * NVOX + v4;
            float4 c = *(const float4*)p;
            float lf = (z > 0)  ? p[-1] : 0.f;
            float rt = (z < 52) ? p[4]  : 0.f;
            float k0 = kd_s[r], k1 = kd_s[RANK + r], k2 = kd_s[2 * RANK + r];
            float4 tt;
            tt.x = k0 * lf  + k1 * c.x + k2 * c.y;
            tt.y = k0 * c.x + k1 * c.y + k2 * c.z;
            tt.z = k0 * c.y + k1 * c.z + k2 * c.w;
            tt.w = k0 * c.z + k1 * c.w + k2 * rt;
            *(float4*)(t_s + r * VOXT + q * 4) = tt;
        }
        __syncthreads();

        // stage 2: out[64][256] = W^T * t
        ull acc[8][4];
#pragma unroll
        for (int i = 0; i < 8; i++)
#pragma unroll
            for (int k = 0; k < 4; k++) acc[i][k] = 0ull;

        const ull* wp = w_s + j0;
        const float* tp = t_s + v0;
        for (int r = 0; r < RANK; r++, wp += COUT, tp += VOXT) {
            ulonglong2 w01 = *(const ulonglong2*)(wp);
            ulonglong2 w23 = *(const ulonglong2*)(wp + 2);
            ulonglong2 w45 = *(const ulonglong2*)(wp + 4);
            ulonglong2 w67 = *(const ulonglong2*)(wp + 6);
            ulonglong2 ta  = *(const ulonglong2*)(tp);
            ulonglong2 tb  = *(const ulonglong2*)(tp + 128);
            ull w[8] = {w01.x, w01.y, w23.x, w23.y, w45.x, w45.y, w67.x, w67.y};
#pragma unroll
            for (int i = 0; i < 8; i++) {
                acc[i][0] = fma2(w[i], ta.x, acc[i][0]);
                acc[i][1] = fma2(w[i], ta.y, acc[i][1]);
                acc[i][2] = fma2(w[i], tb.x, acc[i][2]);
                acc[i][3] = fma2(w[i], tb.y, acc[i][3]);
            }
        }

        const ull one2 = pk2(1.f, 1.f);
#pragma unroll
        for (int i = 0; i < 8; i++) {
            int j = j0 + i;
            ull bb = pk2(b_s[j], b_s[j]);
#pragma unroll
            for (int k = 0; k < 4; k++) acc[i][k] = fma2(bb, one2, acc[i][k]);
            float* o = out + (size_t)j * NVOX + vbase + v0;
            *(ulonglong2*)(o)       = make_ulonglong2(acc[i][0], acc[i][1]);
            *(ulonglong2*)(o + 128) = make_ulonglong2(acc[i][2], acc[i][3]);
        }
        __syncthreads();
    }
}

extern "C" void kernel_launch(void* const* d_in, const int* in_sizes, int n_in,
                              void* d_out, int out_size) {
    const float* x     = (const float*)d_in[0];
    const float* Ukh   = (const float*)d_in[1];
    const float* Ukw   = (const float*)d_in[2];
    const float* Ukd   = (const float*)d_in[3];
    const float* Ucin  = (const float*)d_in[4];
    const float* Ucout = (const float*)d_in[5];
    const float* bias  = (const float*)d_in[6];
    float* out = (float*)d_out;

    float *bufA, *bufB;
    cudaGetSymbolAddress((void**)&bufA, g_bufA);
    cudaGetSymbolAddress((void**)&bufB, g_bufB);

    cudaFuncSetAttribute(k_pointwise, cudaFuncAttributeMaxDynamicSharedMemorySize, PW_SMEM);
    cudaFuncSetAttribute(k_dproj, cudaFuncAttributeMaxDynamicSharedMemorySize, DPROJ_SMEM);

    // one full wave each: 148 SMs x 2 CTAs
    k_pointwise<<<296, 224, PW_SMEM>>>(x, Ucin);
    dim3 g2(DIM / TW, DIM / TH, RANK);     // 7 x 7 x 53
    k_convHW<<<g2, 256>>>(bufA, bufB, Ukh, Ukw);
    k_dproj<<<296, 256, DPROJ_SMEM>>>(bufB, Ukd, Ucout, bias, out);
}

// round 9
// speedup vs baseline: 1.2497x; 1.0119x over previous
#include <cuda_runtime.h>

#define RANK 53
#define RPAD 56
#define CIN  32
#define COUT 64
#define DIM  56
#define NVOX (56*56*56)   // 175616
#define STRH (56*56)
#define STRW 56
#define TH 8
#define TW 8
#define VOXT 128
#define NT   (NVOX / VOXT) // 1372

__device__ float g_bufA[RANK * NVOX];
__device__ float g_bufB[RANK * NVOX];

typedef unsigned long long ull;

__device__ __forceinline__ ull pk2(float lo, float hi) {
    ull r; asm("mov.b64 %0, {%1, %2};" : "=l"(r) : "f"(lo), "f"(hi)); return r;
}
__device__ __forceinline__ ull fma2(ull a, ull b, ull c) {
    ull d; asm("fma.rn.f32x2 %0, %1, %2, %3;" : "=l"(d) : "l"(a), "l"(b), "l"(c)); return d;
}
__device__ __forceinline__ void cpa16(float* smem_dst, const float* gsrc) {
    unsigned s = (unsigned)__cvta_generic_to_shared(smem_dst);
    asm volatile("cp.async.cg.shared.global [%0], [%1], 16;" :: "r"(s), "l"(gsrc));
}
#define CPA_COMMIT() asm volatile("cp.async.commit_group;" ::: "memory")
#define CPA_WAIT1()  asm volatile("cp.async.wait_group 1;"  ::: "memory")

// ---------- Kernel 1: pointwise Cin -> RANK (persistent, cp.async 2-buffer) ----------
__global__ __launch_bounds__(224, 4)
void k_pointwise(const float* __restrict__ x, const float* __restrict__ Ucin) {
    __shared__ ull   w_s[CIN * RPAD];        // 14 KB
    __shared__ float x_s[2][CIN * VOXT];     // 2 x 16 KB

    const int tid = threadIdx.x;
    const int GRID = gridDim.x;

    int t = blockIdx.x;
    if (t < NT)
        for (int i = tid; i < CIN * 32; i += 224) {
            int c = i >> 5, q = i & 31;
            cpa16(x_s[0] + c * VOXT + q * 4, x + (size_t)c * NVOX + t * VOXT + q * 4);
        }
    CPA_COMMIT();

    for (int i = tid; i < CIN * RPAD; i += 224) {
        int c = i / RPAD, r = i % RPAD;
        float v = (r < RANK) ? Ucin[c * RANK + r] : 0.f;
        w_s[i] = pk2(v, v);
    }

    if (t + GRID < NT)
        for (int i = tid; i < CIN * 32; i += 224) {
            int c = i >> 5, q = i & 31;
            cpa16(x_s[1] + c * VOXT + q * 4, x + (size_t)c * NVOX + (t + GRID) * VOXT + q * 4);
        }
    CPA_COMMIT();

    const int warp = tid >> 5;
    const int lane = tid & 31;
    const int r0 = warp * 8;
    const int v0 = lane * 4;

    int p = 0;
    for (; t < NT; t += GRID, p ^= 1) {
        CPA_WAIT1();
        __syncthreads();
        const float* xs = x_s[p];

        ull acc[8][2];
#pragma unroll
        for (int i = 0; i < 8; i++) { acc[i][0] = 0ull; acc[i][1] = 0ull; }

        const ull* wp = w_s + r0;
        const float* xp = xs + v0;
        for (int c = 0; c < CIN; c++, wp += RPAD, xp += VOXT) {
            ulonglong2 w01 = *(const ulonglong2*)(wp);
            ulonglong2 w23 = *(const ulonglong2*)(wp + 2);
            ulonglong2 w45 = *(const ulonglong2*)(wp + 4);
            ulonglong2 w67 = *(const ulonglong2*)(wp + 6);
            ulonglong2 xa  = *(const ulonglong2*)(xp);
            ull w[8] = {w01.x, w01.y, w23.x, w23.y, w45.x, w45.y, w67.x, w67.y};
#pragma unroll
            for (int i = 0; i < 8; i++) {
                acc[i][0] = fma2(w[i], xa.x, acc[i][0]);
                acc[i][1] = fma2(w[i], xa.y, acc[i][1]);
            }
        }

#pragma unroll
        for (int i = 0; i < 8; i++) {
            int r = r0 + i;
            if (r < RANK)
                *(ulonglong2*)(g_bufA + (size_t)r * NVOX + t * VOXT + v0) =
                    make_ulonglong2(acc[i][0], acc[i][1]);
        }
        __syncthreads();

        int tn = t + 2 * GRID;
        if (tn < NT)
            for (int i = tid; i < CIN * 32; i += 224) {
                int c = i >> 5, q = i & 31;
                cpa16(x_s[p] + c * VOXT + q * 4, x + (size_t)c * NVOX + tn * VOXT + q * 4);
            }
        CPA_COMMIT();
    }
}

// ---------- Kernel 2: full separable 3D conv (H, W, then D) per rank ----------
__global__ __launch_bounds__(256)
void k_convHWD(const float* __restrict__ in, float* __restrict__ out,
               const float* __restrict__ Ukh, const float* __restrict__ Ukw,
               const float* __restrict__ Ukd) {
    __shared__ float s [(TH + 2) * (TW + 2) * DIM];   // 22.4 KB
    __shared__ float s2[TH * TW * DIM];               // 14.3 KB

    int r  = blockIdx.z;
    int h0 = blockIdx.y * TH;
    int w0 = blockIdx.x * TW;
    const float* base = in + (size_t)r * NVOX;

    const int NLOAD4 = (TH + 2) * (TW + 2) * (DIM / 4);
    for (int i = threadIdx.x; i < NLOAD4; i += 256) {
        int dq = i % (DIM / 4);
        int t  = i / (DIM / 4);
        int lw = t % (TW + 2);
        int lh = t / (TW + 2);
        int gh = h0 + lh - 1, gw = w0 + lw - 1;
        float4 val = make_float4(0.f, 0.f, 0.f, 0.f);
        if (gh >= 0 && gh < DIM && gw >= 0 && gw < DIM)
            val = *(const float4*)(base + gh * STRH + gw * STRW + dq * 4);
        *(float4*)(s + (lh * (TW + 2) + lw) * DIM + dq * 4) = val;
    }
    __syncthreads();

    float kh[3] = {Ukh[r], Ukh[RANK + r], Ukh[2 * RANK + r]};
    float kw[3] = {Ukw[r], Ukw[RANK + r], Ukw[2 * RANK + r]};
    float kd[3] = {Ukd[r], Ukd[RANK + r], Ukd[2 * RANK + r]};
    float kk[9];
#pragma unroll
    for (int i = 0; i < 3; i++)
#pragma unroll
        for (int j = 0; j < 3; j++) kk[i * 3 + j] = kh[i] * kw[j];

    // pass 1: HW conv s -> s2
    const int NOUT4 = TH * TW * (DIM / 4);   // 896
    for (int o = threadIdx.x; o < NOUT4; o += 256) {
        int dq = o % (DIM / 4);
        int t  = o / (DIM / 4);
        int lw = t % TW;
        int lh = t / TW;
        float4 acc = make_float4(0.f, 0.f, 0.f, 0.f);
#pragma unroll
        for (int i = 0; i < 3; i++)
#pragma unroll
            for (int j = 0; j < 3; j++) {
                const float4 v = *(const float4*)(s + ((lh + i) * (TW + 2) + (lw + j)) * DIM + dq * 4);
                float c = kk[i * 3 + j];
                acc.x += c * v.x; acc.y += c * v.y;
                acc.z += c * v.z; acc.w += c * v.w;
            }
        *(float4*)(s2 + (lh * TW + lw) * DIM + dq * 4) = acc;
    }
    __syncthreads();

    // pass 2: D conv s2 -> global (zero pad at line ends; lines fully in tile)
    float* obase = out + (size_t)r * NVOX;
    for (int o = threadIdx.x; o < NOUT4; o += 256) {
        int dq = o % (DIM / 4);
        int t  = o / (DIM / 4);
        int lw = t % TW;
        int lh = t / TW;
        const float* line = s2 + (lh * TW + lw) * DIM;
        int z = dq * 4;
        float4 c = *(const float4*)(line + z);
        float lf = (z > 0)  ? line[z - 1] : 0.f;
        float rt = (z < 52) ? line[z + 4] : 0.f;
        float4 oq;
        oq.x = kd[0] * lf  + kd[1] * c.x + kd[2] * c.y;
        oq.y = kd[0] * c.x + kd[1] * c.y + kd[2] * c.z;
        oq.z = kd[0] * c.y + kd[1] * c.z + kd[2] * c.w;
        oq.w = kd[0] * c.z + kd[1] * c.w + kd[2] * rt;
        *(float4*)(obase + (h0 + lh) * STRH + (w0 + lw) * STRW + z) = oq;
    }
}

// ---------- Kernel 3: pure GEMM RANK -> 64 + bias (persistent, cp.async 2-buffer) ----------
// Dynamic smem: t_s[2][53*128]f [0,54272); w_s ull[53*64] [54272,81408); b_s f[64] [81408,81664)
#define DPROJ_SMEM 81664
__global__ __launch_bounds__(256, 2)
void k_dproj(const float* __restrict__ in, const float* __restrict__ Ucout,
             const float* __restrict__ bias, float* __restrict__ out) {
    extern __shared__ char dsm[];
    float* t_s[2] = {(float*)dsm, (float*)(dsm + 27136)};
    ull*   w_s = (ull*)(dsm + 54272);
    float* b_s = (float*)(dsm + 81408);

    const int tid = threadIdx.x;
    const int GRID = gridDim.x;

    int t = blockIdx.x;
    if (t < NT)
        for (int i = tid; i < RANK * 32; i += 256) {
            int r = i >> 5, q = i & 31;
            cpa16(t_s[0] + r * VOXT + q * 4, in + (size_t)r * NVOX + t * VOXT + q * 4);
        }
    CPA_COMMIT();

    for (int i = tid; i < RANK * COUT; i += 256) {
        float v = Ucout[i];
        w_s[i] = pk2(v, v);
    }
    if (tid < COUT) b_s[tid] = bias[tid];

    if (t + GRID < NT)
        for (int i = tid; i < RANK * 32; i += 256) {
            int r = i >> 5, q = i & 31;
            cpa16(t_s[1] + r * VOXT + q * 4, in + (size_t)r * NVOX + (t + GRID) * VOXT + q * 4);
        }
    CPA_COMMIT();

    const int warp = tid >> 5;
    const int lane = tid & 31;
    const int j0 = warp * 8;
    const int v0 = lane * 4;

    int p = 0;
    for (; t < NT; t += GRID, p ^= 1) {
        CPA_WAIT1();
        __syncthreads();
        const float* ts = t_s[p];

        ull acc[8][2];
#pragma unroll
        for (int i = 0; i < 8; i++) { acc[i][0] = 0ull; acc[i][1] = 0ull; }

        const ull* wp = w_s + j0;
        const float* tp = ts + v0;
        for (int r = 0; r < RANK; r++, wp += COUT, tp += VOXT) {
            ulonglong2 w01 = *(const ulonglong2*)(wp);
            ulonglong2 w23 = *(const ulonglong2*)(wp + 2);
            ulonglong2 w45 = *(const ulonglong2*)(wp + 4);
            ulonglong2 w67 = *(const ulonglong2*)(wp + 6);
            ulonglong2 ta  = *(const ulonglong2*)(tp);
            ull w[8] = {w01.x, w01.y, w23.x, w23.y, w45.x, w45.y, w67.x, w67.y};
#pragma unroll
            for (int i = 0; i < 8; i++) {
                acc[i][0] = fma2(w[i], ta.x, acc[i][0]);
                acc[i][1] = fma2(w[i], ta.y, acc[i][1]);
            }
        }

        const ull one2 = pk2(1.f, 1.f);
#pragma unroll
        for (int i = 0; i < 8; i++) {
            int j = j0 + i;
            ull bb = pk2(b_s[j], b_s[j]);
            acc[i][0] = fma2(bb, one2, acc[i][0]);
            acc[i][1] = fma2(bb, one2, acc[i][1]);
            *(ulonglong2*)(out + (size_t)j * NVOX + t * VOXT + v0) =
                make_ulonglong2(acc[i][0], acc[i][1]);
        }
        __syncthreads();

        int tn = t + 2 * GRID;
        if (tn < NT)
            for (int i = tid; i < RANK * 32; i += 256) {
                int r = i >> 5, q = i & 31;
                cpa16(t_s[p] + r * VOXT + q * 4, in + (size_t)r * NVOX + tn * VOXT + q * 4);
            }
        CPA_COMMIT();
    }
}

extern "C" void kernel_launch(void* const* d_in, const int* in_sizes, int n_in,
                              void* d_out, int out_size) {
    const float* x     = (const float*)d_in[0];
    const float* Ukh   = (const float*)d_in[1];
    const float* Ukw   = (const float*)d_in[2];
    const float* Ukd   = (const float*)d_in[3];
    const float* Ucin  = (const float*)d_in[4];
    const float* Ucout = (const float*)d_in[5];
    const float* bias  = (const float*)d_in[6];
    float* out = (float*)d_out;

    float *bufA, *bufB;
    cudaGetSymbolAddress((void**)&bufA, g_bufA);
    cudaGetSymbolAddress((void**)&bufB, g_bufB);

    cudaFuncSetAttribute(k_dproj, cudaFuncAttributeMaxDynamicSharedMemorySize, DPROJ_SMEM);

    k_pointwise<<<592, 224>>>(x, Ucin);                    // 4 CTAs/SM, one wave
    dim3 g2(DIM / TW, DIM / TH, RANK);                     // 7 x 7 x 53
    k_convHWD<<<g2, 256>>>(bufA, bufB, Ukh, Ukw, Ukd);
    k_dproj<<<296, 256, DPROJ_SMEM>>>(bufB, Ucout, bias, out);  // 2 CTAs/SM, one wave
}